// round 7
// baseline (speedup 1.0000x reference)
#include <cuda_runtime.h>
#include <math.h>

// Batched SPD projection: per 64x64 real matrix A,
//   A = Q T Q^H  (Hessenberg + complex single-shift QR),
//   QR chase: warp0 = bulge chase (syncwarp-only, shuffle mailbox),
//             warp1 = Q-rotation consumer via acquire/release ring buffer.
//   F = f(T) by Parlett (packed in lower triangle of H), M = Q F Q^H,
//   out = 0.5*(Re(M) + Re(M)^T).

#define N 64
#define LDH 65
#define ULPF 1.1920929e-7f
#define MAXSWEEPS 1920
#define RING 128

__device__ __forceinline__ float2 cadd(float2 a, float2 b){ return make_float2(a.x+b.x, a.y+b.y); }
__device__ __forceinline__ float2 csub(float2 a, float2 b){ return make_float2(a.x-b.x, a.y-b.y); }
__device__ __forceinline__ float2 cmulc(float2 a, float2 b){ return make_float2(a.x*b.x-a.y*b.y, a.x*b.y+a.y*b.x); }
__device__ __forceinline__ float cabs1(float2 a){ return fabsf(a.x)+fabsf(a.y); }
__device__ __forceinline__ float cabs2f(float2 a){ return a.x*a.x+a.y*a.y; }

// left Givens on (row k, row k+1):  a' = c*a + s*b ; b' = c*b - conj(s)*a
__device__ __forceinline__ void rotL(float2& a, float2& b, float c, float2 s){
    float2 na = make_float2(c*a.x + s.x*b.x - s.y*b.y, c*a.y + s.x*b.y + s.y*b.x);
    float2 nb = make_float2(c*b.x - (s.x*a.x + s.y*a.y), c*b.y - (s.x*a.y - s.y*a.x));
    a = na; b = nb;
}
// right Givens on (col k, col k+1): a' = c*a + conj(s)*b ; b' = c*b - s*a
__device__ __forceinline__ void rotR(float2& a, float2& b, float c, float2 s){
    float2 na = make_float2(c*a.x + s.x*b.x + s.y*b.y, c*a.y + s.x*b.y - s.y*b.x);
    float2 nb = make_float2(c*b.x - (s.x*a.x - s.y*a.y), c*b.y - (s.x*a.y + s.y*a.x));
    a = na; b = nb;
}

__device__ __forceinline__ unsigned ld_acq(unsigned* p){
    unsigned v;
    asm volatile("ld.acquire.cta.u32 %0, [%1];" : "=r"(v) : "l"(p) : "memory");
    return v;
}
__device__ __forceinline__ void st_rel(unsigned* p, unsigned v){
    asm volatile("st.release.cta.u32 [%0], %1;" :: "l"(p), "r"(v) : "memory");
}

__global__ void __launch_bounds__(64, 3)
spd_project_kernel(const float* __restrict__ X, float* __restrict__ OUT, int nmat)
{
    extern __shared__ float2 sm[];
    float2* H = sm;              // Hessenberg -> T (upper); F packed strict-lower; later G; later Re(M) in .x
    float2* Q = sm + N * LDH;

    __shared__ float  s_red[2];
    __shared__ float  s_v[N];
    __shared__ float  s_fd[N];
    __shared__ float4 s_ring[RING];   // {k as int bits, c, s.x, s.y}
    __shared__ unsigned s_P, s_C;

    const int tid = threadIdx.x;
    const int g = blockIdx.x;
    if (g >= nmat) return;
    const float* A = X + (size_t)g * (N * N);
    float* Og = OUT + (size_t)g * (N * N);

    if (tid == 0) { s_P = 0u; s_C = 0u; }

    // ---------------- load A, Q = I ----------------
    for (int idx = tid; idx < N * N; idx += 64) {
        int i = idx >> 6, j = idx & 63;
        H[i * LDH + j] = make_float2(A[idx], 0.f);
        Q[i * LDH + j] = make_float2((i == j) ? 1.f : 0.f, 0.f);
    }
    __syncthreads();

    // ---------------- Hessenberg reduction (real; .y stays 0) ----------------
    for (int k = 0; k < N - 2; k++) {
        const int m = N - 1 - k;
        float t = 0.f;
        { int row = k + 2 + tid; if (row < N) { float h = H[row * LDH + k].x; t = h * h; } }
        #pragma unroll
        for (int off = 16; off >= 1; off >>= 1) t += __shfl_xor_sync(0xffffffffu, t, off);
        if ((tid & 31) == 0) s_red[tid >> 5] = t;
        __syncthreads();
        const float sigma = s_red[0] + s_red[1];
        if (sigma > 0.f) {   // uniform across threads
            float x0 = H[(k + 1) * LDH + k].x;
            float mu = sqrtf(x0 * x0 + sigma);
            float v0 = (x0 <= 0.f) ? (x0 - mu) : (-sigma / (x0 + mu));
            float beta = 2.f * v0 * v0 / (sigma + v0 * v0);
            float inv_v0 = 1.f / v0;
            if (tid < m) s_v[tid] = (tid == 0) ? 1.f : H[(k + 1 + tid) * LDH + k].x * inv_v0;
            __syncthreads();
            { int j = k + tid;
              if (j < N) {
                  float w = 0.f;
                  for (int i = 0; i < m; i++) w += s_v[i] * H[(k + 1 + i) * LDH + j].x;
                  w *= beta;
                  for (int i = 0; i < m; i++) H[(k + 1 + i) * LDH + j].x -= s_v[i] * w;
              } }
            __syncthreads();
            { int i = tid;
              float w = 0.f, wq = 0.f;
              for (int l = 0; l < m; l++) w += H[i * LDH + k + 1 + l].x * s_v[l];
              w *= beta;
              for (int l = 0; l < m; l++) H[i * LDH + k + 1 + l].x -= w * s_v[l];
              for (int l = 0; l < m; l++) wq += Q[i * LDH + k + 1 + l].x * s_v[l];
              wq *= beta;
              for (int l = 0; l < m; l++) Q[i * LDH + k + 1 + l].x -= wq * s_v[l];
              if (i >= k + 2) H[i * LDH + k].x = 0.f;
            }
            __syncthreads();
        } else {
            __syncthreads();
        }
    }

    // ================ warp-specialized complex single-shift QR ================
    if (tid < 32) {
        // ---- warp 0: bulge chase on H (syncwarp only) ----
        const unsigned FULL = 0xffffffffu;
        const int lane = tid;
        int its = 0, totit = 0, hi = N - 1;
        unsigned Pl = 0, Cl = 0;
        float2 nf = make_float2(0.f, 0.f), ng = make_float2(0.f, 0.f); // lane31's next (f,g)

        while (true) {
            // deflation scan (redundant; benign same-value write races)
            while (hi > 0) {
                float sub = cabs1(H[hi * LDH + hi - 1]);
                float dd = cabs1(H[(hi - 1) * LDH + hi - 1]) + cabs1(H[hi * LDH + hi]);
                if (sub <= ULPF * dd + 1e-30f) {
                    H[hi * LDH + hi - 1] = make_float2(0.f, 0.f);
                    hi--; its = 0;
                } else break;
            }
            if (hi == 0 || totit >= MAXSWEEPS) break;
            totit++; its++;
            int lo = hi;
            while (lo > 0) {
                float sub = cabs1(H[lo * LDH + lo - 1]);
                float dd = cabs1(H[(lo - 1) * LDH + lo - 1]) + cabs1(H[lo * LDH + lo]);
                if (sub <= ULPF * dd + 1e-30f) {
                    H[lo * LDH + lo - 1] = make_float2(0.f, 0.f);
                    break;
                }
                lo--;
            }
            float2 sig;
            if ((its % 10) == 0) {   // exceptional shift
                sig = H[hi * LDH + hi];
                sig.x += 0.75f * cabs1(H[hi * LDH + hi - 1]);
            } else {                 // Wilkinson shift from trailing 2x2
                float2 a = H[(hi - 1) * LDH + hi - 1], b = H[(hi - 1) * LDH + hi];
                float2 cc = H[hi * LDH + hi - 1],      d2 = H[hi * LDH + hi];
                float2 tr = make_float2(0.5f * (a.x + d2.x), 0.5f * (a.y + d2.y));
                float2 u = make_float2(0.5f * (a.x - d2.x), 0.5f * (a.y - d2.y));
                float2 disc = cadd(cmulc(u, u), cmulc(b, cc));
                float mm = sqrtf(disc.x * disc.x + disc.y * disc.y);
                float re = sqrtf(fmaxf(0.5f * (mm + disc.x), 0.f));
                float im = sqrtf(fmaxf(0.5f * (mm - disc.x), 0.f));
                im = copysignf(im, disc.y);
                float2 sq = make_float2(re, im);
                float2 e1 = cadd(tr, sq), e2 = csub(tr, sq);
                sig = (cabs2f(csub(e1, d2)) < cabs2f(csub(e2, d2))) ? e1 : e2;
            }

            for (int k = lo; k < hi; k++) {
                float2 f, gg;
                if (k == lo) {
                    f = csub(H[lo * LDH + lo], sig);
                    gg = H[(lo + 1) * LDH + lo];
                } else {
                    f.x  = __shfl_sync(FULL, nf.x, 31);
                    f.y  = __shfl_sync(FULL, nf.y, 31);
                    gg.x = __shfl_sync(FULL, ng.x, 31);
                    gg.y = __shfl_sync(FULL, ng.y, 31);
                }
                float ag = cabs2f(gg), af = cabs2f(f);
                float c; float2 s, r;
                if (ag == 0.f) {
                    c = 1.f; s = make_float2(0.f, 0.f); r = f;
                } else if (af == 0.f) {
                    float gn = sqrtf(ag); float gi = 1.f / gn;
                    c = 0.f; s = make_float2(gg.x * gi, -gg.y * gi); r = make_float2(gn, 0.f);
                } else {
                    float irf = rsqrtf(af), ird = rsqrtf(af + ag);
                    float fa = af * irf;                 // sqrt(af)
                    c = fa * ird;
                    float sc = irf * ird;
                    s = make_float2((f.x * gg.x + f.y * gg.y) * sc,
                                    (f.y * gg.x - f.x * gg.y) * sc);
                    float rs = (af + ag) * ird * irf;    // sqrt(af+ag)/sqrt(af)
                    r = make_float2(f.x * rs, f.y * rs);
                }

                // publish (k,c,s) for warp1's Q apply
                if (lane == 0) {
                    if (Pl - Cl >= RING) {
                        do { Cl = ld_acq(&s_C); } while (Pl - Cl >= RING);
                    }
                    s_ring[Pl & (RING - 1)] = make_float4(__int_as_float(k), c, s.x, s.y);
                    st_rel(&s_P, Pl + 1);
                }
                Pl++;

                if (lane < 31) {
                    // left: rows k,k+1 ; cols k+2..N-1 (2 per lane)
                    int j = k + 2 + lane;
                    if (j < N) {
                        float2 a = H[k * LDH + j], b = H[(k + 1) * LDH + j];
                        rotL(a, b, c, s);
                        H[k * LDH + j] = a; H[(k + 1) * LDH + j] = b;
                    }
                    j += 31;
                    if (j < N) {
                        float2 a = H[k * LDH + j], b = H[(k + 1) * LDH + j];
                        rotL(a, b, c, s);
                        H[k * LDH + j] = a; H[(k + 1) * LDH + j] = b;
                    }
                    // right: rows 0..k-1 ; cols k,k+1 (2 per lane)
                    int i = lane;
                    if (i < k) {
                        float2 a = H[i * LDH + k], b = H[i * LDH + k + 1];
                        rotR(a, b, c, s);
                        H[i * LDH + k] = a; H[i * LDH + k + 1] = b;
                    }
                    i += 31;
                    if (i < k) {
                        float2 a = H[i * LDH + k], b = H[i * LDH + k + 1];
                        rotR(a, b, c, s);
                        H[i * LDH + k] = a; H[i * LDH + k + 1] = b;
                    }
                } else {
                    // corner lane: subdiag r, bulge-zero, 2x2 both-sided, bulge row, next (f,g)
                    if (k > lo) {
                        H[k * LDH + k - 1] = r;
                        H[(k + 1) * LDH + k - 1] = make_float2(0.f, 0.f);
                    }
                    float2 p00 = H[k * LDH + k],       p01 = H[k * LDH + k + 1];
                    float2 p10 = H[(k + 1) * LDH + k], p11 = H[(k + 1) * LDH + k + 1];
                    rotL(p00, p10, c, s);
                    rotL(p01, p11, c, s);
                    rotR(p00, p01, c, s);
                    rotR(p10, p11, c, s);
                    H[k * LDH + k] = p00;       H[k * LDH + k + 1] = p01;
                    H[(k + 1) * LDH + k] = p10; H[(k + 1) * LDH + k + 1] = p11;
                    float2 ggn = make_float2(0.f, 0.f);
                    if (k + 2 <= hi) {
                        float2 b2 = H[(k + 2) * LDH + k + 1];
                        ggn = make_float2(s.x * b2.x + s.y * b2.y, s.x * b2.y - s.y * b2.x); // conj(s)*b2
                        H[(k + 2) * LDH + k] = ggn;
                        H[(k + 2) * LDH + k + 1] = make_float2(c * b2.x, c * b2.y);
                    }
                    nf = p10; ng = ggn;
                }
                __syncwarp(FULL);
            }
        }
        // sentinel for warp 1
        if (lane == 0) {
            if (Pl - Cl >= RING) {
                do { Cl = ld_acq(&s_C); } while (Pl - Cl >= RING);
            }
            s_ring[Pl & (RING - 1)] = make_float4(__int_as_float(-1), 0.f, 0.f, 0.f);
            st_rel(&s_P, Pl + 1);
        }
    } else {
        // ---- warp 1: Q-rotation consumer (fixed row ownership -> no intra-warp sync) ----
        const int lane = tid - 32;
        unsigned done = 0;
        bool alive = true;
        while (alive) {
            unsigned p;
            do { p = ld_acq(&s_P); } while (p == done);
            while (done < p) {
                float4 v = s_ring[done & (RING - 1)];
                done++;
                int k = __float_as_int(v.x);
                if (k < 0) { alive = false; break; }
                float c = v.y; float2 s = make_float2(v.z, v.w);
                float2 a = Q[lane * LDH + k], b = Q[lane * LDH + k + 1];
                rotR(a, b, c, s);
                Q[lane * LDH + k] = a; Q[lane * LDH + k + 1] = b;
                a = Q[(lane + 32) * LDH + k]; b = Q[(lane + 32) * LDH + k + 1];
                rotR(a, b, c, s);
                Q[(lane + 32) * LDH + k] = a; Q[(lane + 32) * LDH + k + 1] = b;
            }
            if (lane == 0) st_rel(&s_C, done);
        }
    }
    __syncthreads();

    // ---------------- lam = |w| + eps*min|w| ----------------
    {
        float2 w = H[tid * LDH + tid];
        float a = sqrtf(cabs2f(w));
        float t = a;
        #pragma unroll
        for (int off = 16; off >= 1; off >>= 1) t = fminf(t, __shfl_xor_sync(0xffffffffu, t, off));
        if ((tid & 31) == 0) s_red[tid >> 5] = t;
        __syncthreads();
        float amin = fminf(s_red[0], s_red[1]);
        s_fd[tid] = a + 1e-6f * amin;
        __syncthreads();
    }

    // ---------------- F = f(T) via Parlett; F[i][j] (i<j) stored at H[j][i] ----------------
    for (int p = 1; p < N; p++) {
        int i = tid, j = i + p;
        if (j < N) {
            float2 Tij = H[i * LDH + j];
            float fdiff = s_fd[i] - s_fd[j];
            float2 num = make_float2(Tij.x * fdiff, Tij.y * fdiff);
            for (int kk = i + 1; kk < j; kk++) {
                float2 Fik = H[kk * LDH + i];
                float2 Tkj = H[kk * LDH + j];
                float2 Tik = H[i * LDH + kk];
                float2 Fkj = H[j * LDH + kk];
                num.x += (Fik.x * Tkj.x - Fik.y * Tkj.y) - (Tik.x * Fkj.x - Tik.y * Fkj.y);
                num.y += (Fik.x * Tkj.y + Fik.y * Tkj.x) - (Tik.x * Fkj.y + Tik.y * Fkj.x);
            }
            float2 den = csub(H[i * LDH + i], H[j * LDH + j]);
            float dd = fmaxf(cabs2f(den), 1e-30f);
            H[j * LDH + i] = make_float2((num.x * den.x + num.y * den.y) / dd,
                                         (num.y * den.x - num.x * den.y) / dd);
        }
        __syncthreads();
    }

    // ---------------- G = Q * F  (stage row in registers, then overwrite H) ----------------
    {
        float2 acc[N];
        const int i = tid;
        for (int j = 0; j < N; j++) {
            float2 qd = Q[i * LDH + j];
            float2 a = make_float2(qd.x * s_fd[j], qd.y * s_fd[j]);
            for (int kk = 0; kk < j; kk++) {
                float2 qv = Q[i * LDH + kk];
                float2 fv = H[j * LDH + kk];
                a.x += qv.x * fv.x - qv.y * fv.y;
                a.y += qv.x * fv.y + qv.y * fv.x;
            }
            acc[j] = a;
        }
        __syncthreads();
        for (int j = 0; j < N; j++) H[i * LDH + j] = acc[j];
    }
    __syncthreads();

    // ---------------- Re(M) = Re(G * Q^H) into H[i][*].x ----------------
    {
        float accr[N];
        const int i = tid;
        for (int j = 0; j < N; j++) {
            float a = 0.f;
            for (int kk = 0; kk < N; kk++) {
                float2 gv = H[i * LDH + kk], qv = Q[j * LDH + kk];
                a += gv.x * qv.x + gv.y * qv.y;
            }
            accr[j] = a;
        }
        for (int j = 0; j < N; j++) H[i * LDH + j].x = accr[j];
    }
    __syncthreads();

    // ---------------- out = 0.5*(Re(M) + Re(M)^T) ----------------
    for (int idx = tid; idx < N * N; idx += 64) {
        int i = idx >> 6, j = idx & 63;
        Og[idx] = 0.5f * (H[i * LDH + j].x + H[j * LDH + i].x);
    }
}

extern "C" void kernel_launch(void* const* d_in, const int* in_sizes, int n_in,
                              void* d_out, int out_size) {
    const float* x = (const float*)d_in[0];
    float* out = (float*)d_out;
    int nmat = in_sizes[0] / (N * N);
    size_t smem = 2 * N * LDH * sizeof(float2);  // 66,560 bytes -> 3 blocks/SM
    cudaFuncSetAttribute(spd_project_kernel,
                         cudaFuncAttributeMaxDynamicSharedMemorySize, (int)smem);
    spd_project_kernel<<<nmat, 64, smem>>>(x, out, nmat);
}

// round 9
// speedup vs baseline: 1.3582x; 1.3582x over previous
#include <cuda_runtime.h>
#include <math.h>

// Batched SPD projection: per 64x64 real matrix A,
//   A = Q T Q^H (Hessenberg + complex single-shift QR),
//   chase: warp0 = left applies + Q[0:32), warp1 = right applies + Q[32:64),
//          warp2-lane0 = corner with register-carried window, publishes (c,s)
//          one step ahead. One __syncthreads per chase step, plus ONE barrier
//          per sweep separating the redundant deflation/shift reads from the
//          chase's first writes (the R8 race).
//   F = f(T) by Parlett (packed in lower triangle of H), M = Q F Q^H,
//   out = 0.5*(Re(M) + Re(M)^T).

#define N 64
#define LDH 65
#define ULPF 1.1920929e-7f
#define MAXSWEEPS 1920
#define NT 96

__device__ __forceinline__ float2 cadd(float2 a, float2 b){ return make_float2(a.x+b.x, a.y+b.y); }
__device__ __forceinline__ float2 csub(float2 a, float2 b){ return make_float2(a.x-b.x, a.y-b.y); }
__device__ __forceinline__ float2 cmulc(float2 a, float2 b){ return make_float2(a.x*b.x-a.y*b.y, a.x*b.y+a.y*b.x); }
__device__ __forceinline__ float cabs1(float2 a){ return fabsf(a.x)+fabsf(a.y); }
__device__ __forceinline__ float cabs2f(float2 a){ return a.x*a.x+a.y*a.y; }

// left Givens on (row k, row k+1):  a' = c*a + s*b ; b' = c*b - conj(s)*a
__device__ __forceinline__ void rotL(float2& a, float2& b, float c, float2 s){
    float2 na = make_float2(c*a.x + s.x*b.x - s.y*b.y, c*a.y + s.x*b.y + s.y*b.x);
    float2 nb = make_float2(c*b.x - (s.x*a.x + s.y*a.y), c*b.y - (s.x*a.y - s.y*a.x));
    a = na; b = nb;
}
// right Givens on (col k, col k+1): a' = c*a + conj(s)*b ; b' = c*b - s*a
__device__ __forceinline__ void rotR(float2& a, float2& b, float c, float2 s){
    float2 na = make_float2(c*a.x + s.x*b.x + s.y*b.y, c*a.y + s.x*b.y - s.y*b.x);
    float2 nb = make_float2(c*b.x - (s.x*a.x - s.y*a.y), c*b.y - (s.x*a.y + s.y*a.x));
    a = na; b = nb;
}

__device__ __forceinline__ void genrot(float2 f, float2 g, float& c, float2& s, float2& r){
    float ag = cabs2f(g), af = cabs2f(f);
    if (ag == 0.f) {
        c = 1.f; s = make_float2(0.f, 0.f); r = f;
    } else if (af == 0.f) {
        float gn = sqrtf(ag), gi = 1.f / gn;
        c = 0.f; s = make_float2(g.x * gi, -g.y * gi); r = make_float2(gn, 0.f);
    } else {
        float irf = rsqrtf(af), ird = rsqrtf(af + ag);
        float fa = af * irf;                 // sqrt(af)
        c = fa * ird;
        float sc = irf * ird;
        s = make_float2((f.x * g.x + f.y * g.y) * sc,
                        (f.y * g.x - f.x * g.y) * sc);   // (f/|f|)*conj(g)/d
        float rs = (af + ag) * ird * irf;    // sqrt(af+ag)/sqrt(af)
        r = make_float2(f.x * rs, f.y * rs);
    }
}

__global__ void __launch_bounds__(NT, 3)
spd_project_kernel(const float* __restrict__ X, float* __restrict__ OUT, int nmat)
{
    extern __shared__ float2 sm[];
    float2* H = sm;              // Hessenberg -> T (upper); F packed strict-lower; later G; Re(M) in .x
    float2* Q = sm + N * LDH;

    __shared__ float  s_red[3];
    __shared__ float  s_v[N];
    __shared__ float  s_fd[N];
    __shared__ float4 s_cs[2];   // double-buffered (c, s.x, s.y) mailbox

    const int tid = threadIdx.x;
    const int warp = tid >> 5;
    const int lane = tid & 31;
    const int g = blockIdx.x;
    if (g >= nmat) return;
    const float* A = X + (size_t)g * (N * N);
    float* Og = OUT + (size_t)g * (N * N);

    // ---------------- load A, Q = I ----------------
    for (int idx = tid; idx < N * N; idx += NT) {
        int i = idx >> 6, j = idx & 63;
        H[i * LDH + j] = make_float2(A[idx], 0.f);
        Q[i * LDH + j] = make_float2((i == j) ? 1.f : 0.f, 0.f);
    }
    __syncthreads();

    // ---------------- Hessenberg reduction (real; .y stays 0) ----------------
    for (int k = 0; k < N - 2; k++) {
        const int m = N - 1 - k;
        float t = 0.f;
        { int row = k + 2 + tid; if (row < N) { float h = H[row * LDH + k].x; t = h * h; } }
        #pragma unroll
        for (int off = 16; off >= 1; off >>= 1) t += __shfl_xor_sync(0xffffffffu, t, off);
        if (lane == 0) s_red[warp] = t;
        __syncthreads();
        const float sigma = s_red[0] + s_red[1] + s_red[2];
        if (sigma > 0.f) {   // uniform across threads
            float x0 = H[(k + 1) * LDH + k].x;
            float mu = sqrtf(x0 * x0 + sigma);
            float v0 = (x0 <= 0.f) ? (x0 - mu) : (-sigma / (x0 + mu));
            float beta = 2.f * v0 * v0 / (sigma + v0 * v0);
            float inv_v0 = 1.f / v0;
            if (tid < m) s_v[tid] = (tid == 0) ? 1.f : H[(k + 1 + tid) * LDH + k].x * inv_v0;
            __syncthreads();
            { int j = k + tid;
              if (j < N) {
                  float w = 0.f;
                  for (int i = 0; i < m; i++) w += s_v[i] * H[(k + 1 + i) * LDH + j].x;
                  w *= beta;
                  for (int i = 0; i < m; i++) H[(k + 1 + i) * LDH + j].x -= s_v[i] * w;
              } }
            __syncthreads();
            if (tid < N) {
              int i = tid;
              float w = 0.f, wq = 0.f;
              for (int l = 0; l < m; l++) w += H[i * LDH + k + 1 + l].x * s_v[l];
              w *= beta;
              for (int l = 0; l < m; l++) H[i * LDH + k + 1 + l].x -= w * s_v[l];
              for (int l = 0; l < m; l++) wq += Q[i * LDH + k + 1 + l].x * s_v[l];
              wq *= beta;
              for (int l = 0; l < m; l++) Q[i * LDH + k + 1 + l].x -= wq * s_v[l];
              if (i >= k + 2) H[i * LDH + k].x = 0.f;
            }
            __syncthreads();
        } else {
            __syncthreads();
        }
    }

    // ---------------- complex single-shift QR; control redundant on all threads ----------------
    int its = 0, totit = 0, hi = N - 1;
    while (true) {
        // deflation scan (redundant; benign same-value write races)
        while (hi > 0) {
            float sub = cabs1(H[hi * LDH + hi - 1]);
            float dd = cabs1(H[(hi - 1) * LDH + hi - 1]) + cabs1(H[hi * LDH + hi]);
            if (sub <= ULPF * dd + 1e-30f) {
                H[hi * LDH + hi - 1] = make_float2(0.f, 0.f);
                hi--; its = 0;
            } else break;
        }
        if (hi == 0 || totit >= MAXSWEEPS) break;
        totit++; its++;
        int lo = hi;
        while (lo > 0) {
            float sub = cabs1(H[lo * LDH + lo - 1]);
            float dd = cabs1(H[(lo - 1) * LDH + lo - 1]) + cabs1(H[lo * LDH + lo]);
            if (sub <= ULPF * dd + 1e-30f) {
                H[lo * LDH + lo - 1] = make_float2(0.f, 0.f);
                break;
            }
            lo--;
        }
        float2 sig;
        if ((its % 10) == 0) {   // exceptional shift
            sig = H[hi * LDH + hi];
            sig.x += 0.75f * cabs1(H[hi * LDH + hi - 1]);
        } else {                 // Wilkinson shift from trailing 2x2
            float2 a = H[(hi - 1) * LDH + hi - 1], b = H[(hi - 1) * LDH + hi];
            float2 cc2 = H[hi * LDH + hi - 1],     d2 = H[hi * LDH + hi];
            float2 tr = make_float2(0.5f * (a.x + d2.x), 0.5f * (a.y + d2.y));
            float2 u = make_float2(0.5f * (a.x - d2.x), 0.5f * (a.y - d2.y));
            float2 disc = cadd(cmulc(u, u), cmulc(b, cc2));
            float mm = sqrtf(disc.x * disc.x + disc.y * disc.y);
            float re = sqrtf(fmaxf(0.5f * (mm + disc.x), 0.f));
            float im = sqrtf(fmaxf(0.5f * (mm - disc.x), 0.f));
            im = copysignf(im, disc.y);
            float2 sq = make_float2(re, im);
            float2 e1 = cadd(tr, sq), e2 = csub(tr, sq);
            sig = (cabs2f(csub(e1, d2)) < cabs2f(csub(e2, d2))) ? e1 : e2;
        }

        // initial rotation for k = lo: all threads compute redundantly
        float c; float2 s, r;
        {
            float2 f0 = csub(H[lo * LDH + lo], sig);
            float2 g0 = H[(lo + 1) * LDH + lo];
            genrot(f0, g0, c, s, r);
        }

        // corner primes its register window
        float2 p00, p01, p02, p10, p11, p12, b1;
        if (tid == 64) {
            p00 = H[lo * LDH + lo];       p01 = H[lo * LDH + lo + 1];
            p10 = H[(lo + 1) * LDH + lo]; p11 = H[(lo + 1) * LDH + lo + 1];
            bool c2 = (lo + 2 < N);
            p02 = c2 ? H[lo * LDH + lo + 2] : make_float2(0.f, 0.f);
            p12 = c2 ? H[(lo + 1) * LDH + lo + 2] : make_float2(0.f, 0.f);
            b1  = (lo + 2 <= hi) ? H[(lo + 2) * LDH + lo + 1] : make_float2(0.f, 0.f);
        }

        // CRITICAL: separate the redundant control-phase READS (deflation scan,
        // shift 2x2, genrot inputs, corner priming) from the chase's first
        // WRITES. Without this, a fast warp's step-lo writes race with slower
        // warps still reading those cells (the R8 bug).
        __syncthreads();

        for (int k = lo; k < hi; k++) {
            if (k > lo && tid < 64) {     // lanes fetch (c,s) published one step ago
                float4 v = s_cs[k & 1];
                c = v.x; s = make_float2(v.y, v.z);
            }
            if (warp == 0) {
                // left: rows k,k+1 ; cols k+3.. (corner owns col k+2)
                int j = k + 3 + lane;
                if (j < N) {
                    float2 a = H[k * LDH + j], b = H[(k + 1) * LDH + j];
                    rotL(a, b, c, s);
                    H[k * LDH + j] = a; H[(k + 1) * LDH + j] = b;
                }
                j += 32;
                if (j < N) {
                    float2 a = H[k * LDH + j], b = H[(k + 1) * LDH + j];
                    rotL(a, b, c, s);
                    H[k * LDH + j] = a; H[(k + 1) * LDH + j] = b;
                }
                // Q rows 0..31
                float2 qa = Q[lane * LDH + k], qb = Q[lane * LDH + k + 1];
                rotR(qa, qb, c, s);
                Q[lane * LDH + k] = qa; Q[lane * LDH + k + 1] = qb;
            } else if (warp == 1) {
                // right: rows 0..k-1 ; cols k,k+1
                int i = lane;
                if (i < k) {
                    float2 a = H[i * LDH + k], b = H[i * LDH + k + 1];
                    rotR(a, b, c, s);
                    H[i * LDH + k] = a; H[i * LDH + k + 1] = b;
                }
                i += 32;
                if (i < k) {
                    float2 a = H[i * LDH + k], b = H[i * LDH + k + 1];
                    rotR(a, b, c, s);
                    H[i * LDH + k] = a; H[i * LDH + k + 1] = b;
                }
                // Q rows 32..63
                int qi = lane + 32;
                float2 qa = Q[qi * LDH + k], qb = Q[qi * LDH + k + 1];
                rotR(qa, qb, c, s);
                Q[qi * LDH + k] = qa; Q[qi * LDH + k + 1] = qb;
            } else if (lane == 0) {
                // corner: register-carried window
                rotL(p00, p10, c, s);
                rotL(p01, p11, c, s);
                bool hascol2 = (k + 2 < N);
                if (hascol2) rotL(p02, p12, c, s);
                float2 bulge = make_float2(0.f, 0.f), b1c = make_float2(0.f, 0.f);
                bool hasbulge = (k + 2 <= hi);
                if (hasbulge) {
                    bulge = make_float2(s.x * b1.x + s.y * b1.y, s.x * b1.y - s.y * b1.x); // conj(s)*b1
                    b1c = make_float2(c * b1.x, c * b1.y);
                }
                rotR(p00, p01, c, s);
                rotR(p10, p11, c, s);
                if (k > lo) H[k * LDH + k - 1] = r;
                H[k * LDH + k] = p00;
                H[k * LDH + k + 1] = p01;
                if (hascol2) H[k * LDH + k + 2] = p02;
                H[(k + 1) * LDH + k] = p10;
                if (hasbulge) {
                    H[(k + 2) * LDH + k] = bulge;
                    H[(k + 2) * LDH + k + 1] = b1c;
                }
                if (k + 1 < hi) {
                    genrot(p10, bulge, c, s, r);             // rotation for step k+1
                    s_cs[(k + 1) & 1] = make_float4(c, s.x, s.y, 0.f);
                    // shift window; cells untouched by this step's rotations load now
                    p00 = p11; p01 = p12; p10 = b1c;
                    p11 = H[(k + 2) * LDH + (k + 2)];
                    p12 = (k + 3 < N) ? H[(k + 2) * LDH + (k + 3)] : make_float2(0.f, 0.f);
                    b1  = (k + 3 <= hi) ? H[(k + 3) * LDH + (k + 2)] : make_float2(0.f, 0.f);
                } else {
                    H[(k + 1) * LDH + (k + 1)] = p11;        // finalize row hi
                    if (hascol2) H[(k + 1) * LDH + (k + 2)] = p12;
                }
            }
            __syncthreads();
            if (tid == 64 && k + 1 < hi) {   // lane-written entry for the next window
                p02 = (k + 3 < N) ? H[(k + 1) * LDH + (k + 3)] : make_float2(0.f, 0.f);
            }
        }
    }
    __syncthreads();

    // ---------------- lam = |w| + eps*min|w| ----------------
    {
        float a = 0.f;
        if (tid < N) { float2 w = H[tid * LDH + tid]; a = sqrtf(cabs2f(w)); }
        float t = (tid < N) ? a : 3.4e38f;
        #pragma unroll
        for (int off = 16; off >= 1; off >>= 1) t = fminf(t, __shfl_xor_sync(0xffffffffu, t, off));
        if (tid < N && lane == 0) s_red[warp] = t;
        __syncthreads();
        float amin = fminf(s_red[0], s_red[1]);
        if (tid < N) s_fd[tid] = a + 1e-6f * amin;
        __syncthreads();
    }

    // ---------------- F = f(T) via Parlett; F[i][j] (i<j) stored at H[j][i] ----------------
    for (int p = 1; p < N; p++) {
        int i = tid, j = i + p;
        if (j < N) {
            float2 Tij = H[i * LDH + j];
            float fdiff = s_fd[i] - s_fd[j];
            float2 num = make_float2(Tij.x * fdiff, Tij.y * fdiff);
            for (int kk = i + 1; kk < j; kk++) {
                float2 Fik = H[kk * LDH + i];
                float2 Tkj = H[kk * LDH + j];
                float2 Tik = H[i * LDH + kk];
                float2 Fkj = H[j * LDH + kk];
                num.x += (Fik.x * Tkj.x - Fik.y * Tkj.y) - (Tik.x * Fkj.x - Tik.y * Fkj.y);
                num.y += (Fik.x * Tkj.y + Fik.y * Tkj.x) - (Tik.x * Fkj.y + Tik.y * Fkj.x);
            }
            float2 den = csub(H[i * LDH + i], H[j * LDH + j]);
            float dd = fmaxf(cabs2f(den), 1e-30f);
            H[j * LDH + i] = make_float2((num.x * den.x + num.y * den.y) / dd,
                                         (num.y * den.x - num.x * den.y) / dd);
        }
        __syncthreads();
    }

    // ---------------- G = Q * F  (stage row in registers, then overwrite H) ----------------
    {
        float2 acc[N];
        if (tid < N) {
            const int i = tid;
            for (int j = 0; j < N; j++) {
                float2 qd = Q[i * LDH + j];
                float2 a = make_float2(qd.x * s_fd[j], qd.y * s_fd[j]);
                for (int kk = 0; kk < j; kk++) {
                    float2 qv = Q[i * LDH + kk];
                    float2 fv = H[j * LDH + kk];   // F[kk][j] packed
                    a.x += qv.x * fv.x - qv.y * fv.y;
                    a.y += qv.x * fv.y + qv.y * fv.x;
                }
                acc[j] = a;
            }
        }
        __syncthreads();
        if (tid < N) {
            for (int j = 0; j < N; j++) H[tid * LDH + j] = acc[j];
        }
    }
    __syncthreads();

    // ---------------- Re(M) = Re(G * Q^H) into H[i][*].x ----------------
    {
        float accr[N];
        if (tid < N) {
            const int i = tid;
            for (int j = 0; j < N; j++) {
                float a = 0.f;
                for (int kk = 0; kk < N; kk++) {
                    float2 gv = H[i * LDH + kk], qv = Q[j * LDH + kk];
                    a += gv.x * qv.x + gv.y * qv.y;   // Re(g * conj(q))
                }
                accr[j] = a;
            }
            for (int j = 0; j < N; j++) H[i * LDH + j].x = accr[j];
        }
    }
    __syncthreads();

    // ---------------- out = 0.5*(Re(M) + Re(M)^T) ----------------
    for (int idx = tid; idx < N * N; idx += NT) {
        int i = idx >> 6, j = idx & 63;
        Og[idx] = 0.5f * (H[i * LDH + j].x + H[j * LDH + i].x);
    }
}

extern "C" void kernel_launch(void* const* d_in, const int* in_sizes, int n_in,
                              void* d_out, int out_size) {
    const float* x = (const float*)d_in[0];
    float* out = (float*)d_out;
    int nmat = in_sizes[0] / (N * N);
    size_t smem = 2 * N * LDH * sizeof(float2);  // 66,560 bytes -> 3 blocks/SM
    cudaFuncSetAttribute(spd_project_kernel,
                         cudaFuncAttributeMaxDynamicSharedMemorySize, (int)smem);
    spd_project_kernel<<<nmat, NT, smem>>>(x, out, nmat);
}